// round 12
// baseline (speedup 1.0000x reference)
#include <cuda_runtime.h>
#include <cuda_bf16.h>
#include <cstdint>

// Shapes (fixed by the problem):
//   x:     [4, 256, 64, 64]
//   h:     [4, 128, 64, 64]   (half-res; h_up = 2x nearest upsample of h)
//   wgt:   [4, 200, 64, 64]   (kernel-gen branch at HALF res: constant over 2x2)
//   out:   [4, 128, 128, 128]
#define B_     4
#define CIN    256
#define COUT   128
#define HHALF  64
#define PHALF  4096        // 64*64
#define CRED   32
#define GROUPS 8
#define GC_    16
#define KK     25          // 5x5
#define SPAN   200         // KK*GROUPS

// Scratch (device globals; allocation inside kernel_launch is forbidden)
__device__ float g_h  [(size_t)B_ * COUT * PHALF];   // 8.4 MB
__device__ float g_wgt[(size_t)B_ * SPAN * PHALF];   // 13.1 MB
__device__ __nv_bfloat16 g_wh[COUT * CIN];           // w bf16 hi (o-major, k-contig)
__device__ __nv_bfloat16 g_wl[COUT * CIN];           // w bf16 lo residual

// ---- packed f32x2 helpers (per-lane identical to fmaf) ---------------------
__device__ __forceinline__ unsigned long long pk2(float a, float b) {
    unsigned long long r;
    asm("mov.b64 %0, {%1, %2};" : "=l"(r) : "f"(a), "f"(b));
    return r;
}
__device__ __forceinline__ void fma2(unsigned long long& d,
                                     unsigned long long a, unsigned long long b) {
    asm("fma.rn.f32x2 %0, %1, %2, %0;" : "+l"(d) : "l"(a), "l"(b));
}
__device__ __forceinline__ void upk2(unsigned long long v, float& lo, float& hi) {
    asm("mov.b64 {%0, %1}, %2;" : "=f"(lo), "=f"(hi) : "l"(v));
}

__device__ __forceinline__ uint32_t smem_u32(const void* p) {
    uint32_t a;
    asm("{ .reg .u64 t; cvta.to.shared.u64 t, %1; cvt.u32.u64 %0, t; }" : "=r"(a) : "l"(p));
    return a;
}
__device__ __forceinline__ void ldmx4(uint32_t* r, uint32_t addr) {
    asm volatile("ldmatrix.sync.aligned.m8n8.x4.shared.b16 {%0,%1,%2,%3}, [%4];"
                 : "=r"(r[0]), "=r"(r[1]), "=r"(r[2]), "=r"(r[3]) : "r"(addr));
}
__device__ __forceinline__ void ldmx2t(uint32_t* r, uint32_t addr) {
    asm volatile("ldmatrix.sync.aligned.m8n8.x2.trans.shared.b16 {%0,%1}, [%2];"
                 : "=r"(r[0]), "=r"(r[1]) : "r"(addr));
}
__device__ __forceinline__ void mma_bf16(float* d, const uint32_t* a, const uint32_t* b) {
    asm volatile(
        "mma.sync.aligned.m16n8k16.row.col.f32.bf16.bf16.f32 "
        "{%0,%1,%2,%3}, {%4,%5,%6,%7}, {%8,%9}, {%0,%1,%2,%3};"
        : "+f"(d[0]), "+f"(d[1]), "+f"(d[2]), "+f"(d[3])
        : "r"(a[0]), "r"(a[1]), "r"(a[2]), "r"(a[3]), "r"(b[0]), "r"(b[1]));
}

// ---------------------------------------------------------------------------
// convw_k: w1x1 fp32 [128][256] -> bf16 hi/lo split (o-major, k-contig)
// ---------------------------------------------------------------------------
__global__ __launch_bounds__(256) void convw_k(const float* __restrict__ w) {
    int i4 = blockIdx.x * 256 + threadIdx.x;           // 8192 quads
    float4 v = *(const float4*)(w + 4 * i4);
    float f[4] = {v.x, v.y, v.z, v.w};
    __nv_bfloat16 hi[4], lo[4];
#pragma unroll
    for (int j = 0; j < 4; j++) {
        hi[j] = __float2bfloat16(f[j]);
        lo[j] = __float2bfloat16(f[j] - __bfloat162float(hi[j]));
    }
    __nv_bfloat162* dh = (__nv_bfloat162*)(g_wh + 4 * i4);
    __nv_bfloat162* dl = (__nv_bfloat162*)(g_wl + 4 * i4);
    dh[0] = __halves2bfloat162(hi[0], hi[1]);
    dh[1] = __halves2bfloat162(hi[2], hi[3]);
    dl[0] = __halves2bfloat162(lo[0], lo[1]);
    dl[1] = __halves2bfloat162(lo[2], lo[3]);
}

// ---------------------------------------------------------------------------
// conv1_mma_k (v2): h = conv1x1 via warp-level bf16 mma.sync, fp32 accum.
//    D = Ah*Bh + Ah*Bl + Al*Bh   (Al*Bl dropped, ~2^-18 relative)
// CTA tile 64o x 64px (was 128x128): grid 512 (was 128), smem 84 KB ->
// 2 CTAs/SM resident, phases overlap across CTAs. 1 __syncthreads per chunk.
// A = w hi/lo rows (row pad 528B); B = x chunk converted in-kernel, [k][px]
// rows pad 144B, fragments via ldmatrix.x2.trans. 8 warps, warp tile 32Mx16N.
// ---------------------------------------------------------------------------
static constexpr int SA_H   = 0;                 // 64 rows * 528 B
static constexpr int SA_L   = 33792;
static constexpr int SB0    = 67584;             // 4 * (32 rows * 144 B)
static constexpr int SB_SZ  = 4608;
static constexpr int SM_TOT = 67584 + 4 * SB_SZ; // 86016 B

__global__ __launch_bounds__(256) void conv1_mma_k(const float* __restrict__ x,
                                                   const float* __restrict__ bias) {
    extern __shared__ char smem[];
    const uint32_t sbase = smem_u32(smem);
    const int tid  = threadIdx.x;
    const int wrp  = tid >> 5;
    const int lane = tid & 31;
    const int b      = blockIdx.z;
    const int o_base = blockIdx.y * 64;
    const int p0     = blockIdx.x * 64;

    const int wm = (wrp & 1) * 32;         // warp M offset (o), 2 tiles
    const int wn = (wrp >> 1) * 16;        // warp N offset (px), 4 tiles

    // ---- load A (w hi/lo rows o_base..o_base+63): 2048 uint4 each ----
    {
        const uint4* sh = (const uint4*)(g_wh + o_base * CIN);
        const uint4* sl = (const uint4*)(g_wl + o_base * CIN);
        for (int u = tid; u < 2048; u += 256) {
            int row = u >> 5, c16 = u & 31;
            *(uint4*)(smem + SA_H + row * 528 + c16 * 16) = sh[u];
            *(uint4*)(smem + SA_L + row * 528 + c16 * 16) = sl[u];
        }
    }

    // ---- B prefetch chunk 0 (32 k-rows x 64 px fp32): 2 float4/thread ----
    const float* xb = x + (size_t)b * CIN * PHALF + p0;
    float4 xr[2];
#pragma unroll
    for (int i = 0; i < 2; i++) {
        int u = tid + i * 256;
        int row = u >> 4, seg = u & 15;
        xr[i] = ((const float4*)(xb + (size_t)row * PHALF))[seg];
    }

    float acc[2][2][4];                    // [mt][nt][frag]
#pragma unroll
    for (int i = 0; i < 2; i++)
#pragma unroll
        for (int j = 0; j < 2; j++)
#pragma unroll
            for (int q = 0; q < 4; q++) acc[i][j][q] = 0.f;

    for (int kc = 0; kc < 8; kc++) {
        const int buf = kc & 1;
        const uint32_t bh_base = sbase + SB0 + (buf * 2 + 0) * SB_SZ;
        const uint32_t bl_base = sbase + SB0 + (buf * 2 + 1) * SB_SZ;

        // convert + store prefetched chunk into smem (hi & lo)
#pragma unroll
        for (int i = 0; i < 2; i++) {
            int u = tid + i * 256;
            int row = u >> 4, seg = u & 15;
            float f[4] = {xr[i].x, xr[i].y, xr[i].z, xr[i].w};
            __nv_bfloat16 hi[4], lo[4];
#pragma unroll
            for (int j = 0; j < 4; j++) {
                hi[j] = __float2bfloat16(f[j]);
                lo[j] = __float2bfloat16(f[j] - __bfloat162float(hi[j]));
            }
            char* ph = smem + SB0 + (buf * 2 + 0) * SB_SZ + row * 144 + seg * 8;
            char* pl = smem + SB0 + (buf * 2 + 1) * SB_SZ + row * 144 + seg * 8;
            ((__nv_bfloat162*)ph)[0] = __halves2bfloat162(hi[0], hi[1]);
            ((__nv_bfloat162*)ph)[1] = __halves2bfloat162(hi[2], hi[3]);
            ((__nv_bfloat162*)pl)[0] = __halves2bfloat162(lo[0], lo[1]);
            ((__nv_bfloat162*)pl)[1] = __halves2bfloat162(lo[2], lo[3]);
        }
        __syncthreads();   // single barrier per chunk (see safety argument)

        // prefetch next chunk (overlaps mma)
        if (kc < 7) {
#pragma unroll
            for (int i = 0; i < 2; i++) {
                int u = tid + i * 256;
                int row = u >> 4, seg = u & 15;
                xr[i] = ((const float4*)(xb + (size_t)((kc + 1) * 32 + row) * PHALF))[seg];
            }
        }

        // ---- mma over this chunk: 2 ksteps of 16 ----
#pragma unroll
        for (int s = 0; s < 2; s++) {
            uint32_t a_h[2][4], a_l[2][4];
            const uint32_t akoff = (uint32_t)(kc * 64 + s * 32 + (lane >> 4) * 16);
#pragma unroll
            for (int mt = 0; mt < 2; mt++) {
                uint32_t arow = (uint32_t)(wm + mt * 16 + (lane & 15));
                ldmx4(a_h[mt], sbase + SA_H + arow * 528 + akoff);
                ldmx4(a_l[mt], sbase + SA_L + arow * 528 + akoff);
            }
            uint32_t b_h[2][2], b_l[2][2];
            const uint32_t brow = (uint32_t)(s * 16 + (lane & 15));
#pragma unroll
            for (int nt = 0; nt < 2; nt++) {
                uint32_t bcol = (uint32_t)((wn + nt * 8) * 2);
                ldmx2t(b_h[nt], bh_base + brow * 144 + bcol);
                ldmx2t(b_l[nt], bl_base + brow * 144 + bcol);
            }
#pragma unroll
            for (int mt = 0; mt < 2; mt++)
#pragma unroll
                for (int nt = 0; nt < 2; nt++) {
                    mma_bf16(acc[mt][nt], a_h[mt], b_h[nt]);
                    mma_bf16(acc[mt][nt], a_h[mt], b_l[nt]);
                    mma_bf16(acc[mt][nt], a_l[mt], b_h[nt]);
                }
        }
    }

    // ---- epilogue: bias + store ----
#pragma unroll
    for (int mt = 0; mt < 2; mt++) {
        int o0 = o_base + wm + mt * 16 + (lane >> 2);
        float bv0 = bias[o0];
        float bv1 = bias[o0 + 8];
#pragma unroll
        for (int nt = 0; nt < 2; nt++) {
            int px = p0 + wn + nt * 8 + (lane & 3) * 2;
            float* d0 = g_h + ((size_t)b * COUT + o0) * PHALF + px;
            float* d1 = g_h + ((size_t)b * COUT + o0 + 8) * PHALF + px;
            *(float2*)d0 = make_float2(acc[mt][nt][0] + bv0, acc[mt][nt][1] + bv0);
            *(float2*)d1 = make_float2(acc[mt][nt][2] + bv1, acc[mt][nt][3] + bv1);
        }
    }
}

// ---------------------------------------------------------------------------
// Kernel 2: kernel-generation branch AT HALF RES (unchanged).
// ---------------------------------------------------------------------------
__global__ __launch_bounds__(256) void kgen_k(const float* __restrict__ wred,
                                              const float* __restrict__ bred,
                                              const float* __restrict__ gamma,
                                              const float* __restrict__ beta,
                                              const float* __restrict__ mean,
                                              const float* __restrict__ var,
                                              const float* __restrict__ wspan,
                                              const float* __restrict__ bspan) {
    __shared__ float pool[6600];
    __shared__ float h_sh[16][64];
    __shared__ float r_sh[CRED][68];

    const int tid = threadIdx.x;
    const int q0  = blockIdx.x * 64;
    const int b   = q0 >> 12;
    const int p0  = q0 & 4095;

    for (int i = tid; i < CRED * COUT; i += 256) {
        int o = i >> 7, c = i & 127;
        pool[c * CRED + o] = wred[i];
    }

    const int oq  = tid >> 5;
    const int pxp = tid & 31;

    float acc[4][2];
#pragma unroll
    for (int i = 0; i < 4; i++) {
        float bv = bred[4 * oq + i];
        acc[i][0] = bv; acc[i][1] = bv;
    }

    const float* hb = g_h + (size_t)b * COUT * PHALF + p0;
    const int hc = tid >> 4, hp4 = tid & 15;

    for (int cc = 0; cc < COUT; cc += 16) {
        __syncthreads();
        *(float4*)&h_sh[hc][4 * hp4] =
            *(const float4*)(hb + (size_t)(cc + hc) * PHALF + 4 * hp4);
        __syncthreads();
#pragma unroll
        for (int c = 0; c < 16; c++) {
            float4 wv = *(const float4*)&pool[(cc + c) * CRED + 4 * oq];
            float2 hv = *(const float2*)&h_sh[c][2 * pxp];
            acc[0][0] += wv.x * hv.x;  acc[0][1] += wv.x * hv.y;
            acc[1][0] += wv.y * hv.x;  acc[1][1] += wv.y * hv.y;
            acc[2][0] += wv.z * hv.x;  acc[2][1] += wv.z * hv.y;
            acc[3][0] += wv.w * hv.x;  acc[3][1] += wv.w * hv.y;
        }
    }

#pragma unroll
    for (int i = 0; i < 4; i++) {
        int o = 4 * oq + i;
        float sc = gamma[o] * rsqrtf(var[o] + 1e-5f);
        float sh = beta[o] - mean[o] * sc;
        float v0 = fmaxf(acc[i][0] * sc + sh, 0.f);
        float v1 = fmaxf(acc[i][1] * sc + sh, 0.f);
        *(float2*)&r_sh[o][2 * pxp] = make_float2(v0, v1);
    }
    __syncthreads();

    for (int i = tid; i < SPAN * CRED; i += 256) {
        int s = i >> 5, oo = i & 31;
        pool[s * 33 + oo] = wspan[i];
    }
    __syncthreads();

    if (tid < 200) {
        const int s0 = (tid >> 3) * 8;
        const int px = (tid & 7) * 8;

        float acc2[8][8];
#pragma unroll
        for (int i = 0; i < 8; i++) {
            float bv = bspan[s0 + i];
#pragma unroll
            for (int j = 0; j < 8; j++) acc2[i][j] = bv;
        }

#pragma unroll 4
        for (int oo = 0; oo < CRED; oo++) {
            float w8[8];
#pragma unroll
            for (int i = 0; i < 8; i++) w8[i] = pool[(s0 + i) * 33 + oo];
            float4 ra = *(const float4*)&r_sh[oo][px];
            float4 rb = *(const float4*)&r_sh[oo][px + 4];
#pragma unroll
            for (int i = 0; i < 8; i++) {
                acc2[i][0] += w8[i] * ra.x;  acc2[i][1] += w8[i] * ra.y;
                acc2[i][2] += w8[i] * ra.z;  acc2[i][3] += w8[i] * ra.w;
                acc2[i][4] += w8[i] * rb.x;  acc2[i][5] += w8[i] * rb.y;
                acc2[i][6] += w8[i] * rb.z;  acc2[i][7] += w8[i] * rb.w;
            }
        }

        float* wb = g_wgt + (size_t)b * SPAN * PHALF + p0 + px;
#pragma unroll
        for (int i = 0; i < 8; i++) {
            float4 v0 = make_float4(acc2[i][0], acc2[i][1], acc2[i][2], acc2[i][3]);
            float4 v1 = make_float4(acc2[i][4], acc2[i][5], acc2[i][6], acc2[i][7]);
            *(float4*)(wb + (size_t)(s0 + i) * PHALF)     = v0;
            *(float4*)(wb + (size_t)(s0 + i) * PHALF + 4) = v1;
        }
    }
}

// ---------------------------------------------------------------------------
// Kernel 3 (v4): involution with pre-collapsed 3x3 weights, 8 channels/block.
// grid 1024 (was 512) to lift the measured grid-occupancy limit.
// ---------------------------------------------------------------------------
__global__ __launch_bounds__(256) void inv_k(float* __restrict__ out) {
    __shared__ float2 hs[8][18][19];     // duplicated halo'd h tile, ~21.9 KB

    const int b   = blockIdx.z;
    const int g   = blockIdx.y >> 1;
    const int ch0 = (blockIdx.y & 1) * 8;
    const int ti = (blockIdx.x >> 2) * 16;
    const int tj = (blockIdx.x & 3) * 16;
    const int tid = threadIdx.x;

    // load 8-channel h tile (+1 halo each side) duplicated, zero pad
    const float* hb = g_h + ((size_t)b * COUT + g * GC_ + ch0) * PHALF;
    for (int e = tid; e < 8 * 324; e += 256) {
        int c   = e / 324;
        int rem = e - c * 324;
        int rr  = rem / 18, cc = rem - rr * 18;
        int gi = ti - 1 + rr, gj = tj - 1 + cc;
        float v = 0.f;
        if ((unsigned)gi < 64u && (unsigned)gj < 64u)
            v = hb[(size_t)c * PHALF + gi * HHALF + gj];
        hs[c][rr][cc] = make_float2(v, v);
    }

    const int jl = tid & 15, il = tid >> 4;
    const int pix = (ti + il) * HHALF + (tj + jl);

    // ---- load 25 weights, collapse to 4 effective 3x3 kernels, pack ----
    unsigned long long wA[9], wB[9];     // (W00,W01) and (W10,W11)
    {
        float wk[KK];
        const float* wgp = g_wgt + ((size_t)b * SPAN + g * KK) * PHALF + pix;
#pragma unroll
        for (int k = 0; k < KK; k++) wk[k] = wgp[(size_t)k * PHALF];

        float P0[3][5], P1[3][5];
#pragma unroll
        for (int kw = 0; kw < 5; kw++) {
            P0[0][kw] = wk[0 + kw] + wk[5 + kw];
            P0[1][kw] = wk[10 + kw] + wk[15 + kw];
            P0[2][kw] = wk[20 + kw];
            P1[0][kw] = wk[0 + kw];
            P1[1][kw] = wk[5 + kw] + wk[10 + kw];
            P1[2][kw] = wk[15 + kw] + wk[20 + kw];
        }
#pragma unroll
        for (int r = 0; r < 3; r++) {
            wA[r * 3 + 0] = pk2(P0[r][0] + P0[r][1], P0[r][0]);
            wA[r * 3 + 1] = pk2(P0[r][2] + P0[r][3], P0[r][1] + P0[r][2]);
            wA[r * 3 + 2] = pk2(P0[r][4],            P0[r][3] + P0[r][4]);
            wB[r * 3 + 0] = pk2(P1[r][0] + P1[r][1], P1[r][0]);
            wB[r * 3 + 1] = pk2(P1[r][2] + P1[r][3], P1[r][1] + P1[r][2]);
            wB[r * 3 + 2] = pk2(P1[r][4],            P1[r][3] + P1[r][4]);
        }
    }

    __syncthreads();

    const int y0 = 2 * (ti + il), x0 = 2 * (tj + jl);
    float* ob = out + (((size_t)b * COUT + g * GC_ + ch0) * 128 + y0) * 128 + x0;

#pragma unroll
    for (int c = 0; c < 8; c++) {
        unsigned long long m[9];
#pragma unroll
        for (int a = 0; a < 3; a++)
#pragma unroll
            for (int d = 0; d < 3; d++)
                m[a * 3 + d] = *(const unsigned long long*)&hs[c][il + a][jl + d];

        unsigned long long accA = 0ull;  // (a00, a01)
        unsigned long long accB = 0ull;  // (a10, a11)
#pragma unroll
        for (int i = 0; i < 9; i++) {
            fma2(accA, wA[i], m[i]);
            fma2(accB, wB[i], m[i]);
        }
        float a00, a01, a10, a11;
        upk2(accA, a00, a01);
        upk2(accB, a10, a11);
        *reinterpret_cast<float2*>(ob + (size_t)c * 16384)       = make_float2(a00, a01);
        *reinterpret_cast<float2*>(ob + (size_t)c * 16384 + 128) = make_float2(a10, a11);
    }
}

// ---------------------------------------------------------------------------
extern "C" void kernel_launch(void* const* d_in, const int* in_sizes, int n_in,
                              void* d_out, int out_size) {
    const float* x      = (const float*)d_in[0];
    const float* w1x1   = (const float*)d_in[1];
    const float* b1x1   = (const float*)d_in[2];
    const float* w_red  = (const float*)d_in[3];
    const float* b_red  = (const float*)d_in[4];
    const float* gamma  = (const float*)d_in[5];
    const float* beta   = (const float*)d_in[6];
    const float* mean   = (const float*)d_in[7];
    const float* var    = (const float*)d_in[8];
    const float* w_span = (const float*)d_in[9];
    const float* b_span = (const float*)d_in[10];
    float* out = (float*)d_out;

    cudaFuncSetAttribute(conv1_mma_k,
                         cudaFuncAttributeMaxDynamicSharedMemorySize, SM_TOT);

    convw_k<<<32, 256>>>(w1x1);
    conv1_mma_k<<<dim3(PHALF / 64, 2, B_), 256, SM_TOT>>>(x, b1x1);
    kgen_k<<<dim3((B_ * PHALF) / 64, 1, 1), 256>>>(w_red, b_red, gamma, beta,
                                                   mean, var, w_span, b_span);
    inv_k<<<dim3(16, GROUPS * 2, B_), 256>>>(out);
}